// round 1
// baseline (speedup 1.0000x reference)
#include <cuda_runtime.h>
#include <math.h>

// ---------------- problem constants ----------------
#define Bz   8
#define Cch  256
#define Hh   64
#define Ww   64
#define HQ   32
#define WQ   32
#define Lq   1024          // HQ*WQ
#define NHh  8
#define HD   8             // ED_QK/NH
#define DV   32            // ED_V/NH
#define BL   8192          // Bz*Lq
#define L2   4096          // Hh*Ww
#define BL2  32768         // Bz*L2

// ---------------- scratch (__device__ globals; allocation-free launch) ----
__device__ float g_X1[1024 * 8192];                 // im2col pos proj (k=c*4+ky*2+kx)
__device__ float g_W1[384 * 1024];                  // packed q/k/v weights
__device__ float g_b1[384];
__device__ float g_P1[384 * 8192];                  // proj out [oc][b*L+l]
__device__ float g_Pattn[(size_t)64 * 1024 * 1024]; // probs [bh][q][k]
__device__ float g_Vr[64 * 1024 * 32];              // V [bh][k][d]
__device__ float g_O1[64 * 1024 * 32];              // attn out [bh][l][d]
__device__ float g_OP[256 * 8192];                  // op [c][b*L+l]
__device__ float g_X2[2304 * 8192];                 // im2col 3x3 pos
__device__ float g_O2[256 * 8192];                  // conv3x3 out
__device__ float g_outpos[8 * 256 * 4096];
__device__ float g_qc[8 * 2048 * 1024];             // [b][flat_ch][l]
__device__ float g_kc[8 * 2048 * 1024];
__device__ float g_vc[8 * 2048 * 1024];
__device__ float g_Sc[64 * 256 * 256];              // cha scores/probs
__device__ float g_oc[8 * 2048 * 1024];
__device__ float g_outcha[8 * 256 * 4096];
__device__ float g_X3[(size_t)4608 * 32768];        // im2col fusion
__device__ float g_O3[256 * 32768];                 // fusion out [oc][b*L2+pix]

// ---------------- generic SGEMM: C[M,N] = A[M,K] * B(K,N or N,K) + bias[m] --
// Requirements (all call sites satisfy): M%128==0, K%16==0, N%BN==0.
template <int BN, bool TRANSB>
__global__ __launch_bounds__(256) void sgemm_kernel(
    const float* __restrict__ A, const float* __restrict__ B,
    float* __restrict__ C, const float* __restrict__ bias,
    int M, int N, int K, long sA, long sB, long sC)
{
    constexpr int BM = 128, BK = 16;
    constexpr int TM = 8, TN = BN / 16;
    __shared__ float As[BK][BM + 4];
    __shared__ float Bs[BK][BN];

    const float* Ab = A + (long)blockIdx.z * sA;
    const float* Bb = B + (long)blockIdx.z * sB;
    float* Cb = C + (long)blockIdx.z * sC;

    const int m0 = blockIdx.y * BM;
    const int n0 = blockIdx.x * BN;
    const int tid = threadIdx.x;
    const int tx = tid & 15, ty = tid >> 4;

    float acc[TM][TN];
#pragma unroll
    for (int i = 0; i < TM; i++)
#pragma unroll
        for (int j = 0; j < TN; j++) acc[i][j] = 0.0f;

    float4 rA[2];
    float4 rB;

    auto loadA = [&](int k0) {
#pragma unroll
        for (int i = 0; i < 2; i++) {
            int f = tid + i * 256;
            int m = f >> 2, kc = (f & 3) << 2;
            rA[i] = *(const float4*)(Ab + (long)(m0 + m) * K + (k0 + kc));
        }
    };
    auto storeA = [&]() {
#pragma unroll
        for (int i = 0; i < 2; i++) {
            int f = tid + i * 256;
            int m = f >> 2, kc = (f & 3) << 2;
            As[kc + 0][m] = rA[i].x; As[kc + 1][m] = rA[i].y;
            As[kc + 2][m] = rA[i].z; As[kc + 3][m] = rA[i].w;
        }
    };
    auto loadB = [&](int k0) {
        if (!TRANSB) {
            constexpr int TOT = BK * BN / 4;       // float4 count
            if (TOT >= 256 || tid < TOT) {
                constexpr int R = BN / 4;          // float4 per k-row
                int kr = tid / R, nc = (tid % R) << 2;
                rB = *(const float4*)(Bb + (long)(k0 + kr) * N + (n0 + nc));
            }
        } else {
            constexpr int TOT = BN * 4;            // BN rows x 4 float4
            if (TOT >= 256 || tid < TOT) {
                int n = tid >> 2, kc = (tid & 3) << 2;
                rB = *(const float4*)(Bb + (long)(n0 + n) * K + (k0 + kc));
            }
        }
    };
    auto storeB = [&]() {
        if (!TRANSB) {
            constexpr int TOT = BK * BN / 4;
            if (TOT >= 256 || tid < TOT) {
                constexpr int R = BN / 4;
                int kr = tid / R, nc = (tid % R) << 2;
                *(float4*)&Bs[kr][nc] = rB;
            }
        } else {
            constexpr int TOT = BN * 4;
            if (TOT >= 256 || tid < TOT) {
                int n = tid >> 2, kc = (tid & 3) << 2;
                Bs[kc + 0][n] = rB.x; Bs[kc + 1][n] = rB.y;
                Bs[kc + 2][n] = rB.z; Bs[kc + 3][n] = rB.w;
            }
        }
    };

    loadA(0); loadB(0);
    storeA(); storeB();
    __syncthreads();

    for (int k0 = BK; k0 < K + BK; k0 += BK) {
        bool more = (k0 < K);
        if (more) { loadA(k0); loadB(k0); }
#pragma unroll
        for (int kk = 0; kk < BK; kk++) {
            float a[TM], bv[TN];
#pragma unroll
            for (int i = 0; i < TM; i++) a[i] = As[kk][ty * TM + i];
#pragma unroll
            for (int j = 0; j < TN; j++) bv[j] = Bs[kk][tx * TN + j];
#pragma unroll
            for (int i = 0; i < TM; i++)
#pragma unroll
                for (int j = 0; j < TN; j++) acc[i][j] += a[i] * bv[j];
        }
        __syncthreads();
        if (more) { storeA(); storeB(); __syncthreads(); }
    }

#pragma unroll
    for (int i = 0; i < TM; i++) {
        int m = m0 + ty * TM + i;
        float bb = bias ? bias[m] : 0.0f;
#pragma unroll
        for (int j = 0; j < TN; j++)
            Cb[(long)m * N + (n0 + tx * TN + j)] = acc[i][j] + bb;
    }
}

// ---------------- small helpers ----------------
__device__ __forceinline__ float warp_max(float v) {
#pragma unroll
    for (int o = 16; o; o >>= 1) v = fmaxf(v, __shfl_xor_sync(0xffffffffu, v, o));
    return v;
}
__device__ __forceinline__ float warp_sum(float v) {
#pragma unroll
    for (int o = 16; o; o >>= 1) v += __shfl_xor_sync(0xffffffffu, v, o);
    return v;
}

// ---------------- kernels ----------------
__global__ void k_pack_w1(const float* __restrict__ Wq, const float* __restrict__ bq,
                          const float* __restrict__ Wk, const float* __restrict__ bk,
                          const float* __restrict__ Wv, const float* __restrict__ bv) {
    int idx = blockIdx.x * 256 + threadIdx.x;   // 0..393215
    if (idx < 64 * 1024)        g_W1[idx] = Wq[idx];
    else if (idx < 128 * 1024)  g_W1[idx] = Wk[idx - 65536];
    else                        g_W1[idx] = Wv[idx - 131072];
    if (idx < 64)               g_b1[idx] = bq[idx];
    else if (idx < 128)         g_b1[idx] = bk[idx - 64];
    else if (idx < 384)         g_b1[idx] = bv[idx - 128];
}

__global__ void k_im2col_x1(const float* __restrict__ x) {
    int idx = blockIdx.x * 256 + threadIdx.x;   // 1024*8192
    int n = idx & 8191, k = idx >> 13;
    int c = k >> 2, ky = (k >> 1) & 1, kx = k & 1;
    int b = n >> 10, l = n & 1023, y = l >> 5, xq = l & 31;
    g_X1[idx] = x[(((b * 256 + c) * 64) + (y * 2 + ky)) * 64 + xq * 2 + kx];
}

// fused pos attention: scores + softmax -> g_Pattn. grid(128, NH, B), block 256
__global__ void k_pos_attn() {
    __shared__ float Ks[8][1024];
    int b = blockIdx.z, h = blockIdx.y;
    int tid = threadIdx.x;
    for (int idx = tid; idx < 8 * 1024; idx += 256) {
        int d = idx >> 10, k = idx & 1023;
        Ks[d][k] = g_P1[(64 + h * 8 + d) * BL + b * 1024 + k];
    }
    __syncthreads();
    int warp = tid >> 5, lane = tid & 31;
    int q = blockIdx.x * 8 + warp;
    float Q[8];
#pragma unroll
    for (int d = 0; d < 8; d++) Q[d] = g_P1[(h * 8 + d) * BL + b * 1024 + q];

    float s[32];
    float mx = -1e30f;
#pragma unroll
    for (int i = 0; i < 32; i++) {
        int k = i * 32 + lane;
        float sc = 0.f;
#pragma unroll
        for (int d = 0; d < 8; d++) sc += Q[d] * Ks[d][k];
        sc *= 0.35355339059327373f;   // hd^-0.5
        s[i] = sc;
        mx = fmaxf(mx, sc);
    }
    mx = warp_max(mx);
    float sum = 0.f;
#pragma unroll
    for (int i = 0; i < 32; i++) { float e = __expf(s[i] - mx); s[i] = e; sum += e; }
    sum = warp_sum(sum);
    float inv = 1.0f / sum;
    float* out = g_Pattn + ((size_t)(b * 8 + h) * 1024 + q) * 1024;
#pragma unroll
    for (int i = 0; i < 32; i++) out[i * 32 + lane] = s[i] * inv;
}

__global__ void k_vr_repack() {
    int idx = blockIdx.x * 256 + threadIdx.x;   // 64*1024*32
    int d = idx & 31, k = (idx >> 5) & 1023, bh = idx >> 15;
    int b = bh >> 3, h = bh & 7;
    g_Vr[idx] = g_P1[(128 + h * 32 + d) * BL + b * 1024 + k];
}

__global__ void k_op_repack() {
    int idx = blockIdx.x * 256 + threadIdx.x;   // 256*8192
    int n = idx & 8191, c = idx >> 13;
    int b = n >> 10, l = n & 1023;
    g_OP[idx] = g_O1[((b * 8 + (c >> 5)) * 1024 + l) * 32 + (c & 31)];
}

__global__ void k_im2col_x2() {
    int idx = blockIdx.x * 256 + threadIdx.x;   // 2304*8192
    int n = idx & 8191, k2 = idx >> 13;
    int c = k2 / 9, tap = k2 - c * 9;
    int dy = tap / 3 - 1, dx = tap - (tap / 3) * 3 - 1;
    int b = n >> 10, l = n & 1023, y = l >> 5, xq = l & 31;
    int yy = y + dy, xx = xq + dx;
    float v = 0.f;
    if ((unsigned)yy < 32u && (unsigned)xx < 32u)
        v = g_OP[c * 8192 + b * 1024 + yy * 32 + xx];
    g_X2[idx] = v;
}

__global__ void k_upsample_residual(const float* __restrict__ x, const float* __restrict__ gamma) {
    int idx = blockIdx.x * 256 + threadIdx.x;   // 8*256*4096
    int pix = idx & 4095, c = (idx >> 12) & 255, b = idx >> 20;
    int Y = pix >> 6, X = pix & 63;
    float sy = Y * 0.5f - 0.25f, sx = X * 0.5f - 0.25f;
    int y0 = (int)floorf(sy); float fy = sy - (float)y0;
    int x0 = (int)floorf(sx); float fx = sx - (float)x0;
    int y1 = min(y0 + 1, 31); y0 = max(y0, 0);
    int x1 = min(x0 + 1, 31); x0 = max(x0, 0);
    const float* p = g_O2 + c * 8192 + b * 1024;
    float v00 = p[y0 * 32 + x0], v01 = p[y0 * 32 + x1];
    float v10 = p[y1 * 32 + x0], v11 = p[y1 * 32 + x1];
    float v = (1.f - fy) * ((1.f - fx) * v00 + fx * v01) + fy * ((1.f - fx) * v10 + fx * v11);
    g_outpos[idx] = x[idx] + gamma[0] * v;
}

__global__ void k_cha_proj(const float* __restrict__ x,
                           const float* __restrict__ Wq, const float* __restrict__ bq,
                           const float* __restrict__ Wk, const float* __restrict__ bk,
                           const float* __restrict__ Wv, const float* __restrict__ bv) {
    int l = blockIdx.x * 256 + threadIdx.x;
    int g = blockIdx.y, b = blockIdx.z;
    int i = l >> 5, j = l & 31;
    const float* xp = x + ((b * 256 + g) * 64) * 64;
    float x00 = xp[(2 * i) * 64 + 2 * j],     x01 = xp[(2 * i) * 64 + 2 * j + 1];
    float x10 = xp[(2 * i + 1) * 64 + 2 * j], x11 = xp[(2 * i + 1) * 64 + 2 * j + 1];
    int base = (b * 2048 + g * 8) * 1024 + l;
#pragma unroll
    for (int h = 0; h < 8; h++) {
        int w = (g * 8 + h) * 4;
        g_qc[base + h * 1024] = Wq[w] * x00 + Wq[w + 1] * x01 + Wq[w + 2] * x10 + Wq[w + 3] * x11 + bq[g * 8 + h];
        g_kc[base + h * 1024] = Wk[w] * x00 + Wk[w + 1] * x01 + Wk[w + 2] * x10 + Wk[w + 3] * x11 + bk[g * 8 + h];
        g_vc[base + h * 1024] = Wv[w] * x00 + Wv[w + 1] * x01 + Wv[w + 2] * x10 + Wv[w + 3] * x11 + bv[g * 8 + h];
    }
}

__global__ void k_cha_softmax() {
    int row = blockIdx.x * 8 + (threadIdx.x >> 5);  // 16384 rows
    int lane = threadIdx.x & 31;
    float* r = g_Sc + row * 256;
    float v[8];
    float mx = -1e30f;
#pragma unroll
    for (int j = 0; j < 8; j++) { v[j] = r[j * 32 + lane] * 0.03125f; mx = fmaxf(mx, v[j]); }
    mx = warp_max(mx);
    float sum = 0.f;
#pragma unroll
    for (int j = 0; j < 8; j++) { v[j] = __expf(v[j] - mx); sum += v[j]; }
    sum = warp_sum(sum);
    float inv = 1.0f / sum;
#pragma unroll
    for (int j = 0; j < 8; j++) r[j * 32 + lane] = v[j] * inv;
}

__global__ void k_ct_residual(const float* __restrict__ x, const float* __restrict__ Wt,
                              const float* __restrict__ bt, const float* __restrict__ gamma) {
    int pix = blockIdx.x * 256 + threadIdx.x;
    int g = blockIdx.y, b = blockIdx.z;
    int Y = pix >> 6, X = pix & 63;
    int p = Y >> 1, ky = Y & 1, q = X >> 1, kx = X & 1;
    float s = bt[g];
    int obase = (b * 2048 + g * 8) * 1024 + p * 32 + q;
#pragma unroll
    for (int i = 0; i < 8; i++)
        s += g_oc[obase + i * 1024] * Wt[(g * 8 + i) * 4 + ky * 2 + kx];
    int idx = ((b * 256 + g) * 4096) + pix;
    g_outcha[idx] = x[idx] + gamma[0] * s;
}

__global__ void k_im2col_x3() {
    int idx = blockIdx.x * 256 + threadIdx.x;   // 4608*32768
    int n = idx & 32767, k3 = idx >> 15;
    int cc = k3 / 9, tap = k3 - cc * 9;
    int dy = tap / 3 - 1, dx = tap - (tap / 3) * 3 - 1;
    int b = n >> 12, pix = n & 4095, Y = pix >> 6, X = pix & 63;
    int YY = Y + dy, XX = X + dx;
    float v = 0.f;
    if ((unsigned)YY < 64u && (unsigned)XX < 64u) {
        const float* src = (cc < 256) ? (g_outpos + ((b * 256 + cc) * 4096))
                                      : (g_outcha + ((b * 256 + cc - 256) * 4096));
        v = src[YY * 64 + XX];
    }
    g_X3[(size_t)idx] = v;
}

__global__ void k_out_permute(float* __restrict__ out) {
    int idx = blockIdx.x * 256 + threadIdx.x;   // 8*256*4096
    int pix = idx & 4095, ocb = idx >> 12;
    int oc = ocb & 255, b = ocb >> 8;
    out[idx] = g_O3[oc * 32768 + b * 4096 + pix];
}

// ---------------- launch ----------------
static float* symaddr(const void* sym) {
    void* p = nullptr;
    cudaGetSymbolAddress(&p, sym);
    return (float*)p;
}

extern "C" void kernel_launch(void* const* d_in, const int* in_sizes, int n_in,
                              void* d_out, int out_size) {
    const float* qkv_pos  = (const float*)d_in[0];
    const float* qkv_cha  = (const float*)d_in[1];
    const float* Wq_pos   = (const float*)d_in[2];
    const float* bq_pos   = (const float*)d_in[3];
    const float* Wk_pos   = (const float*)d_in[4];
    const float* bk_pos   = (const float*)d_in[5];
    const float* Wv_pos   = (const float*)d_in[6];
    const float* bv_pos   = (const float*)d_in[7];
    const float* Wo_pos   = (const float*)d_in[8];
    const float* bo_pos   = (const float*)d_in[9];
    const float* gamma_pos= (const float*)d_in[10];
    const float* Wq_cha   = (const float*)d_in[11];
    const float* bq_cha   = (const float*)d_in[12];
    const float* Wk_cha   = (const float*)d_in[13];
    const float* bk_cha   = (const float*)d_in[14];
    const float* Wv_cha   = (const float*)d_in[15];
    const float* bv_cha   = (const float*)d_in[16];
    const float* Wt_cha   = (const float*)d_in[17];
    const float* bt_cha   = (const float*)d_in[18];
    const float* gamma_cha= (const float*)d_in[19];
    const float* Wf       = (const float*)d_in[20];
    const float* bf       = (const float*)d_in[21];
    float* out = (float*)d_out;

    float* pX1    = symaddr(g_X1);
    float* pW1    = symaddr(g_W1);
    float* pb1    = symaddr(g_b1);
    float* pP1    = symaddr(g_P1);
    float* pPattn = symaddr(g_Pattn);
    float* pVr    = symaddr(g_Vr);
    float* pO1    = symaddr(g_O1);
    float* pX2    = symaddr(g_X2);
    float* pO2    = symaddr(g_O2);
    float* pqc    = symaddr(g_qc);
    float* pkc    = symaddr(g_kc);
    float* pvc    = symaddr(g_vc);
    float* pSc    = symaddr(g_Sc);
    float* poc    = symaddr(g_oc);
    float* pX3    = symaddr(g_X3);
    float* pO3    = symaddr(g_O3);

    // ---- POS branch ----
    k_pack_w1<<<(384 * 1024) / 256, 256>>>(Wq_pos, bq_pos, Wk_pos, bk_pos, Wv_pos, bv_pos);
    k_im2col_x1<<<(1024 * 8192) / 256, 256>>>(qkv_pos);
    // qkv proj GEMM: (384 x 1024) @ (1024 x 8192)
    sgemm_kernel<64, false><<<dim3(8192 / 64, 384 / 128, 1), 256>>>(
        pW1, pX1, pP1, pb1, 384, 8192, 1024, 0, 0, 0);
    // fused scores + softmax
    k_pos_attn<<<dim3(128, NHh, Bz), 256>>>();
    k_vr_repack<<<(64 * 1024 * 32) / 256, 256>>>();
    // P @ V (batched 64): (1024 x 1024) @ (1024 x 32)
    sgemm_kernel<32, false><<<dim3(1, 1024 / 128, 64), 256>>>(
        pPattn, pVr, pO1, nullptr, 1024, 32, 1024,
        (long)1024 * 1024, (long)1024 * 32, (long)1024 * 32);
    k_op_repack<<<(256 * 8192) / 256, 256>>>();
    k_im2col_x2<<<(2304 * 8192) / 256, 256>>>();
    // conv3x3 pos GEMM: (256 x 2304) @ (2304 x 8192)
    sgemm_kernel<64, false><<<dim3(8192 / 64, 256 / 128, 1), 256>>>(
        Wo_pos, pX2, pO2, bo_pos, 256, 8192, 2304, 0, 0, 0);
    k_upsample_residual<<<(8 * 256 * 4096) / 256, 256>>>(qkv_pos, gamma_pos);

    // ---- CHA branch ----
    k_cha_proj<<<dim3(1024 / 256, 256, Bz), 256>>>(qkv_cha, Wq_cha, bq_cha, Wk_cha, bk_cha, Wv_cha, bv_cha);
    // S = qc @ kc^T (batched 64): (256 x 1024) @ (1024 x 256)
    sgemm_kernel<64, true><<<dim3(256 / 64, 256 / 128, 64), 256>>>(
        pqc, pkc, pSc, nullptr, 256, 256, 1024,
        (long)256 * 1024, (long)256 * 1024, (long)256 * 256);
    k_cha_softmax<<<(64 * 256) / 8, 256>>>();
    // oc = P @ vc (batched 64): (256 x 256) @ (256 x 1024)
    sgemm_kernel<64, false><<<dim3(1024 / 64, 256 / 128, 64), 256>>>(
        pSc, pvc, poc, nullptr, 256, 1024, 256,
        (long)256 * 256, (long)256 * 1024, (long)256 * 1024);
    k_ct_residual<<<dim3(4096 / 256, 256, Bz), 256>>>(qkv_cha, Wt_cha, bt_cha, gamma_cha);

    // ---- fusion conv 512->256 3x3 ----
    k_im2col_x3<<<(int)(((size_t)4608 * 32768) / 256), 256>>>();
    sgemm_kernel<64, false><<<dim3(32768 / 64, 256 / 128, 1), 256>>>(
        Wf, pX3, pO3, bf, 256, 32768, 4608, 0, 0, 0);
    k_out_permute<<<(8 * 256 * 4096) / 256, 256>>>(out);
}